// round 1
// baseline (speedup 1.0000x reference)
#include <cuda_runtime.h>
#include <math.h>

// Problem dims (fixed by the dataset)
#define BB 16
#define CC 512
#define SS 1024           // H*W = 32*32
#define PER_B (CC*SS)     // 524288 elems per batch

// ---------------- scratch (static device memory; no allocs) ----------------
__device__ float g_h[(size_t)BB*SS*CC];           // normalized, transposed [B,S,C]
__device__ float g_qkv[(size_t)BB*SS*3*CC];       // [B,S,3C]
__device__ float g_scores[(size_t)BB*SS*SS];      // [B,S,S]
__device__ float g_ao[(size_t)BB*SS*CC];          // attn output [B,S,C]
__device__ float g_psum[BB*64], g_psq[BB*64];
__device__ float g_stats[BB*2];                   // mean, inv_std per batch

// ---------------- GroupNorm stats: partial reduce ----------------
__global__ void gn_partial(const float* __restrict__ x) {
    int b = blockIdx.y, chunk = blockIdx.x, t = threadIdx.x;
    const float* p = x + (size_t)b*PER_B + (size_t)chunk*8192;
    float s = 0.f, q = 0.f;
#pragma unroll
    for (int i = 0; i < 32; i++) { float v = p[t + i*256]; s += v; q += v*v; }
    __shared__ float ss[8], sq[8];
    for (int o = 16; o > 0; o >>= 1) {
        s += __shfl_down_sync(0xffffffffu, s, o);
        q += __shfl_down_sync(0xffffffffu, q, o);
    }
    if ((t & 31) == 0) { ss[t >> 5] = s; sq[t >> 5] = q; }
    __syncthreads();
    if (t == 0) {
        float S2 = 0.f, Q2 = 0.f;
#pragma unroll
        for (int i = 0; i < 8; i++) { S2 += ss[i]; Q2 += sq[i]; }
        g_psum[b*64 + chunk] = S2; g_psq[b*64 + chunk] = Q2;
    }
}

__global__ void gn_finalize() {
    int b = threadIdx.x;
    if (b < BB) {
        float s = 0.f, q = 0.f;
        for (int i = 0; i < 64; i++) { s += g_psum[b*64+i]; q += g_psq[b*64+i]; }
        float mean = s * (1.f/(float)PER_B);
        float var  = q * (1.f/(float)PER_B) - mean*mean;
        g_stats[2*b]   = mean;
        g_stats[2*b+1] = rsqrtf(var + 1e-5f);
    }
}

// ---------------- normalize + transpose [B,C,S] -> [B,S,C] ----------------
__global__ void norm_transpose(const float* __restrict__ x,
                               const float* __restrict__ gw,
                               const float* __restrict__ gb) {
    __shared__ float tile[32][33];
    int b = blockIdx.z;
    int s0 = blockIdx.x * 32, c0 = blockIdx.y * 32;
    int tx = threadIdx.x, ty = threadIdx.y;
    const float* xp = x + (size_t)b * PER_B;
#pragma unroll
    for (int i = 0; i < 4; i++) {
        int c = c0 + ty + i*8;
        tile[ty + i*8][tx] = xp[(size_t)c*SS + s0 + tx];
    }
    __syncthreads();
    float mean = g_stats[2*b], inv = g_stats[2*b+1];
    int c = c0 + tx;
    float w  = gw[c] * inv;
    float bb = gb[c] - mean * w;
    float* hp = g_h + (size_t)b * SS * CC;
#pragma unroll
    for (int i = 0; i < 4; i++) {
        int s = s0 + ty + i*8;
        hp[(size_t)s*CC + c] = tile[tx][ty + i*8] * w + bb;
    }
}

// ---------------- generic tiled SGEMM ----------------
// C[M,N] = alpha * A[M,K] * op(B) (+ bias) ; A row-major (lda), batched via z.
// BTRANS=true : B is [N,K] row-major (NT gemm)
// BTRANS=false: B is [K,N] row-major (NN gemm)
// EPI: 0 = +bias[n]; 1 = *alpha; 3 = proj epilogue (+bias, +residual, write transposed NCHW)
template<int EPI, bool BTRANS>
__global__ __launch_bounds__(256, 2)
void gemm_tiled(const float* __restrict__ A, int lda, long long sA,
                const float* __restrict__ Bm, int ldb, long long sB,
                float* __restrict__ Cm, int ldc, long long sC,
                const float* __restrict__ bias,
                const float* __restrict__ resid,
                float alpha, int M, int N, int K) {
    __shared__ float As[16][132];
    __shared__ float Bs[16][132];
    int z = blockIdx.z;
    A  += (size_t)z * sA;
    Bm += (size_t)z * sB;
    Cm += (size_t)z * sC;
    int m0 = blockIdx.y * 128, n0 = blockIdx.x * 128;
    int tid = threadIdx.x;
    int tx = tid & 15, ty = tid >> 4;

    float acc[8][8];
#pragma unroll
    for (int i = 0; i < 8; i++)
#pragma unroll
        for (int j = 0; j < 8; j++) acc[i][j] = 0.f;

    int ar = tid >> 2, ac = (tid & 3) * 4;   // A / NT-B loader coords
    int bk_ = tid >> 5, bn_ = (tid & 31) * 4; // NN-B loader coords

    for (int k0 = 0; k0 < K; k0 += 16) {
#pragma unroll
        for (int r = 0; r < 2; r++) {
            int row = ar + r*64;
            float4 v = *(const float4*)&A[(size_t)(m0+row)*lda + k0 + ac];
            As[ac+0][row] = v.x; As[ac+1][row] = v.y;
            As[ac+2][row] = v.z; As[ac+3][row] = v.w;
        }
        if constexpr (BTRANS) {
#pragma unroll
            for (int r = 0; r < 2; r++) {
                int row = ar + r*64;
                float4 v = *(const float4*)&Bm[(size_t)(n0+row)*ldb + k0 + ac];
                Bs[ac+0][row] = v.x; Bs[ac+1][row] = v.y;
                Bs[ac+2][row] = v.z; Bs[ac+3][row] = v.w;
            }
        } else {
#pragma unroll
            for (int r = 0; r < 2; r++) {
                int kk = bk_ + r*8;
                float4 v = *(const float4*)&Bm[(size_t)(k0+kk)*ldb + n0 + bn_];
                *(float4*)&Bs[kk][bn_] = v;
            }
        }
        __syncthreads();
#pragma unroll
        for (int k = 0; k < 16; k++) {
            float a[8], b[8];
            *(float4*)(a)   = *(const float4*)&As[k][ty*8];
            *(float4*)(a+4) = *(const float4*)&As[k][ty*8 + 4];
            *(float4*)(b)   = *(const float4*)&Bs[k][tx*8];
            *(float4*)(b+4) = *(const float4*)&Bs[k][tx*8 + 4];
#pragma unroll
            for (int i = 0; i < 8; i++)
#pragma unroll
                for (int j = 0; j < 8; j++)
                    acc[i][j] = fmaf(a[i], b[j], acc[i][j]);
        }
        __syncthreads();
    }

#pragma unroll
    for (int i = 0; i < 8; i++) {
        int m = m0 + ty*8 + i;
#pragma unroll
        for (int j = 0; j < 8; j++) {
            int n = n0 + tx*8 + j;
            float v = acc[i][j];
            if constexpr (EPI == 0) {
                Cm[(size_t)m*ldc + n] = v + bias[n];
            } else if constexpr (EPI == 1) {
                Cm[(size_t)m*ldc + n] = v * alpha;
            } else { // proj: out[b, n(=c), s] = v + bias + x
                size_t idx = ((size_t)(m >> 10) * CC + n) * SS + (m & 1023);
                Cm[idx] = v + bias[n] + resid[idx];
            }
        }
    }
}

// ---------------- row softmax over 1024-wide rows ----------------
__global__ void softmax_rows(float* __restrict__ sc) {
    float* row = sc + (size_t)blockIdx.x * SS;
    int t = threadIdx.x;
    float v[4];
#pragma unroll
    for (int i = 0; i < 4; i++) v[i] = row[t + i*256];
    float m = fmaxf(fmaxf(v[0], v[1]), fmaxf(v[2], v[3]));
    __shared__ float red[8];
    for (int o = 16; o > 0; o >>= 1) m = fmaxf(m, __shfl_xor_sync(0xffffffffu, m, o));
    if ((t & 31) == 0) red[t >> 5] = m;
    __syncthreads();
    float mm = fmaxf(fmaxf(fmaxf(red[0], red[1]), fmaxf(red[2], red[3])),
                     fmaxf(fmaxf(red[4], red[5]), fmaxf(red[6], red[7])));
    float s = 0.f;
#pragma unroll
    for (int i = 0; i < 4; i++) { v[i] = __expf(v[i] - mm); s += v[i]; }
    for (int o = 16; o > 0; o >>= 1) s += __shfl_xor_sync(0xffffffffu, s, o);
    __syncthreads();
    if ((t & 31) == 0) red[t >> 5] = s;
    __syncthreads();
    float tot = ((red[0]+red[1]) + (red[2]+red[3])) + ((red[4]+red[5]) + (red[6]+red[7]));
    float invs = 1.f / tot;
#pragma unroll
    for (int i = 0; i < 4; i++) row[t + i*256] = v[i] * invs;
}

// ---------------- launch ----------------
extern "C" void kernel_launch(void* const* d_in, const int* in_sizes, int n_in,
                              void* d_out, int out_size) {
    const float* x      = (const float*)d_in[0];
    const float* gn_w   = (const float*)d_in[1];
    const float* gn_b   = (const float*)d_in[2];
    const float* qkv_w  = (const float*)d_in[3];
    const float* qkv_b  = (const float*)d_in[4];
    const float* proj_w = (const float*)d_in[5];
    const float* proj_b = (const float*)d_in[6];
    float* out = (float*)d_out;

    float* h;  cudaGetSymbolAddress((void**)&h,  g_h);
    float* qkv;cudaGetSymbolAddress((void**)&qkv,g_qkv);
    float* sc; cudaGetSymbolAddress((void**)&sc, g_scores);
    float* ao; cudaGetSymbolAddress((void**)&ao, g_ao);

    // 1. GroupNorm stats
    gn_partial<<<dim3(64, BB), 256>>>(x);
    gn_finalize<<<1, 32>>>();

    // 2. normalize + transpose -> g_h [B,S,C]
    norm_transpose<<<dim3(SS/32, CC/32, BB), dim3(32, 8)>>>(x, gn_w, gn_b);

    // 3. QKV GEMM: [16384,512] x [1536,512]^T -> g_qkv [B,S,3C]
    gemm_tiled<0, true><<<dim3(3*CC/128, BB*SS/128, 1), 256>>>(
        h, CC, 0LL, qkv_w, CC, 0LL, qkv, 3*CC, 0LL, qkv_b, nullptr, 1.f,
        BB*SS, 3*CC, CC);

    // 4. scores = scale * Q K^T (batched, NT), q at +0, k at +512 within 3C rows
    gemm_tiled<1, true><<<dim3(SS/128, SS/128, BB), 256>>>(
        qkv,       3*CC, (long long)SS*3*CC,
        qkv + CC,  3*CC, (long long)SS*3*CC,
        sc, SS, (long long)SS*SS,
        nullptr, nullptr, 0.044194173824159216f /*1/sqrt(512)*/,
        SS, SS, CC);

    // 5. softmax rows
    softmax_rows<<<BB*SS, 256>>>(sc);

    // 6. attn @ V (batched, NN), v at +1024 within 3C rows
    gemm_tiled<1, false><<<dim3(CC/128, SS/128, BB), 256>>>(
        sc, SS, (long long)SS*SS,
        qkv + 2*CC, 3*CC, (long long)SS*3*CC,
        ao, CC, (long long)SS*CC,
        nullptr, nullptr, 1.f,
        SS, CC, SS);

    // 7. proj + bias + residual, written transposed to NCHW output
    gemm_tiled<3, true><<<dim3(CC/128, BB*SS/128, 1), 256>>>(
        ao, CC, 0LL, proj_w, CC, 0LL, out, CC, 0LL, proj_b, x, 1.f,
        BB*SS, CC, CC);
}

// round 3
// speedup vs baseline: 1.4741x; 1.4741x over previous
#include <cuda_runtime.h>
#include <cuda_bf16.h>
#include <cstdint>
#include <math.h>

#define BB 16
#define CC 512
#define SS 1024
#define PER_B (CC*SS)

typedef __nv_bfloat16 bf16;

// ---------------- scratch (__device__ globals; no allocs) ----------------
__device__ float g_psum[BB*64], g_psq[BB*64], g_stats[BB*2];
__device__ bf16  g_h2 [(size_t)BB*SS*1536];   // norm'd [B*S, hi|lo|hi] (A-side)
__device__ bf16  g_w1 [1536*1536];            // qkv_w split  (B-side: hi|hi|lo)
__device__ bf16  g_w2 [512*1536];             // proj_w split (B-side)
__device__ bf16  g_q2 [(size_t)BB*SS*1536];   // Q (A-side)
__device__ bf16  g_k2 [(size_t)BB*SS*1536];   // K (B-side)
__device__ bf16  g_v2 [(size_t)BB*CC*3072];   // V transposed [B,C, hi|hi|lo over S] (B-side)
__device__ bf16  g_p2 [(size_t)BB*SS*3072];   // probs [B*S, hi|lo|hi] (A-side)
__device__ bf16  g_ao2[(size_t)BB*SS*1536];   // attn out (A-side)
__device__ float g_sc [(size_t)BB*SS*SS];     // scores fp32

// ---------------- helpers ----------------
__device__ __forceinline__ uint32_t smem_u32(const void* p) {
    uint32_t a;
    asm("{ .reg .u64 t; cvta.to.shared.u64 t, %1; cvt.u32.u64 %0, t; }" : "=r"(a) : "l"(p));
    return a;
}
#define CP_ASYNC16(dst, src) \
    asm volatile("cp.async.cg.shared.global [%0], [%1], 16;" :: "r"(dst), "l"(src) : "memory")
#define CP_COMMIT() asm volatile("cp.async.commit_group;" ::: "memory")
#define CP_WAIT0()  asm volatile("cp.async.wait_group 0;" ::: "memory")
#define CP_WAIT1()  asm volatile("cp.async.wait_group 1;" ::: "memory")
#define LDM_X4(r0,r1,r2,r3,addr) \
    asm volatile("ldmatrix.sync.aligned.m8n8.x4.shared.b16 {%0,%1,%2,%3}, [%4];" \
        : "=r"(r0),"=r"(r1),"=r"(r2),"=r"(r3) : "r"(addr))
#define MMA16816(d, a, b0, b1) \
    asm volatile("mma.sync.aligned.m16n8k16.row.col.f32.bf16.bf16.f32 " \
        "{%0,%1,%2,%3}, {%4,%5,%6,%7}, {%8,%9}, {%0,%1,%2,%3};" \
        : "+f"((d)[0]), "+f"((d)[1]), "+f"((d)[2]), "+f"((d)[3]) \
        : "r"((a)[0]), "r"((a)[1]), "r"((a)[2]), "r"((a)[3]), "r"(b0), "r"(b1))

__device__ __forceinline__ void split2(float v, bf16& hi, bf16& lo) {
    hi = __float2bfloat16(v);
    lo = __float2bfloat16(v - __bfloat162float(hi));
}

// ---------------- GroupNorm stats ----------------
__global__ void gn_partial(const float* __restrict__ x) {
    int b = blockIdx.y, chunk = blockIdx.x, t = threadIdx.x;
    const float* p = x + (size_t)b*PER_B + (size_t)chunk*8192;
    float s = 0.f, q = 0.f;
#pragma unroll
    for (int i = 0; i < 32; i++) { float v = p[t + i*256]; s += v; q += v*v; }
    __shared__ float ss_[8], sq_[8];
    for (int o = 16; o > 0; o >>= 1) {
        s += __shfl_down_sync(0xffffffffu, s, o);
        q += __shfl_down_sync(0xffffffffu, q, o);
    }
    if ((t & 31) == 0) { ss_[t >> 5] = s; sq_[t >> 5] = q; }
    __syncthreads();
    if (t == 0) {
        float S2 = 0.f, Q2 = 0.f;
#pragma unroll
        for (int i = 0; i < 8; i++) { S2 += ss_[i]; Q2 += sq_[i]; }
        g_psum[b*64 + chunk] = S2; g_psq[b*64 + chunk] = Q2;
    }
}
__global__ void gn_finalize() {
    int b = threadIdx.x;
    if (b < BB) {
        float s = 0.f, q = 0.f;
        for (int i = 0; i < 64; i++) { s += g_psum[b*64+i]; q += g_psq[b*64+i]; }
        float mean = s * (1.f/(float)PER_B);
        float var  = q * (1.f/(float)PER_B) - mean*mean;
        g_stats[2*b] = mean; g_stats[2*b+1] = rsqrtf(var + 1e-5f);
    }
}

// ---------------- normalize + transpose + split -> g_h2 [B*S, 1536] ----------------
__global__ void norm_split(const float* __restrict__ x,
                           const float* __restrict__ gw,
                           const float* __restrict__ gb) {
    __shared__ float tile[32][33];
    int b = blockIdx.z;
    int s0 = blockIdx.x * 32, c0 = blockIdx.y * 32;
    int tx = threadIdx.x, ty = threadIdx.y;
    const float* xp = x + (size_t)b * PER_B;
#pragma unroll
    for (int i = 0; i < 4; i++) {
        int c = c0 + ty + i*8;
        tile[ty + i*8][tx] = xp[(size_t)c*SS + s0 + tx];
    }
    __syncthreads();
    float mean = g_stats[2*b], inv = g_stats[2*b+1];
    int c = c0 + tx;
    float w  = gw[c] * inv;
    float bias = gb[c] - mean * w;
#pragma unroll
    for (int i = 0; i < 4; i++) {
        int s = s0 + ty + i*8;
        float v = tile[tx][ty + i*8] * w + bias;
        bf16 hi, lo; split2(v, hi, lo);
        bf16* row = g_h2 + ((size_t)b*SS + s) * 1536;
        row[c] = hi; row[512 + c] = lo; row[1024 + c] = hi;
    }
}

// ---------------- weight split (B-side [hi|hi|lo]) ----------------
__global__ void wsplit(const float* __restrict__ src, bf16* __restrict__ dst, int total) {
    int i = blockIdx.x * 256 + threadIdx.x;
    if (i < total) {
        int r = i >> 9, c = i & 511;
        bf16 hi, lo; split2(src[i], hi, lo);
        bf16* row = dst + (size_t)r * 1536;
        row[c] = hi; row[512 + c] = hi; row[1024 + c] = lo;
    }
}

// ---------------- HMMA GEMM: 128x128 CTA tile, 4 warps (64x64 each), BK=32 ----------------
// NT: out[m,n] = sum_k A[m,k]*B[n,k]
// EPI: 0 = QKV split-out, 1 = scores*scale, 2 = AV split-out, 3 = proj+bias+resid (NCHW)
#define DYN_SMEM 69632
#define STAGE_BYTES 20480        // A(10240) + B(10240); row stride 80B

__device__ __forceinline__ void prefetch_tile(char* smem, int stage,
    const bf16* __restrict__ A, int lda, const bf16* __restrict__ B, int ldb,
    int m0, int n0, int k0, int tid)
{
    char* as = smem + stage*STAGE_BYTES;
    char* bs = as + 10240;
    const bf16* ag = A + (size_t)(m0 + tid)*lda + k0;
    const bf16* bg = B + (size_t)(n0 + tid)*ldb + k0;
    uint32_t asw = smem_u32(as + tid*80);
    uint32_t bsw = smem_u32(bs + tid*80);
#pragma unroll
    for (int g = 0; g < 4; g++) {
        CP_ASYNC16(asw + g*16, (const void*)(ag + g*8));
        CP_ASYNC16(bsw + g*16, (const void*)(bg + g*8));
    }
}

template<int EPI>
__global__ __launch_bounds__(128, 2)
void mm_gemm(const bf16* __restrict__ A, int lda, long long sA,
             const bf16* __restrict__ B, int ldb, long long sB,
             float* __restrict__ Out,
             const float* __restrict__ bias,
             const float* __restrict__ resid,
             float scale, int K)
{
    extern __shared__ char smem[];
    int tid = threadIdx.x, lane = tid & 31, wid = tid >> 5;
    int wm = wid >> 1, wn = wid & 1;
    int z = blockIdx.z;
    int m0 = blockIdx.y * 128, n0 = blockIdx.x * 128;
    A += (size_t)z * sA;
    B += (size_t)z * sB;

    float acc[4][8][4];
#pragma unroll
    for (int i = 0; i < 4; i++)
#pragma unroll
        for (int j = 0; j < 8; j++)
#pragma unroll
            for (int r = 0; r < 4; r++) acc[i][j][r] = 0.f;

    // ldmatrix per-thread byte offsets within tile
    // A: rows m (lane&15), kgran (lane>>4)          -> matrices a0,a1,a2,a3
    // B: rows n (lane&7)+((lane>>4)<<3), kgran (lane>>3)&1 -> b0/b1 for 2 n-frags
    uint32_t a_off = (uint32_t)((wm*64 + (lane & 15)) * 80 + (lane >> 4) * 16);
    uint32_t b_off = (uint32_t)((wn*64 + (lane & 7) + ((lane >> 4) << 3)) * 80
                                + ((lane >> 3) & 1) * 16);
    uint32_t smem_base = smem_u32(smem);

    int nch = K >> 5;
    prefetch_tile(smem, 0, A, lda, B, ldb, m0, n0, 0, tid);
    CP_COMMIT();

    for (int c = 0; c < nch; c++) {
        int st = c & 1;
        if (c + 1 < nch) {
            prefetch_tile(smem, st ^ 1, A, lda, B, ldb, m0, n0, (c+1)*32, tid);
            CP_COMMIT();
            CP_WAIT1();
        } else {
            CP_WAIT0();
        }
        __syncthreads();

        uint32_t as_b = smem_base + st*STAGE_BYTES + a_off;
        uint32_t bs_b = smem_base + st*STAGE_BYTES + 10240 + b_off;
#pragma unroll
        for (int ks = 0; ks < 2; ks++) {
            uint32_t a[4][4], b[4][4];
#pragma unroll
            for (int mf = 0; mf < 4; mf++)
                LDM_X4(a[mf][0], a[mf][1], a[mf][2], a[mf][3], as_b + mf*1280 + ks*32);
#pragma unroll
            for (int nf2 = 0; nf2 < 4; nf2++)
                LDM_X4(b[nf2][0], b[nf2][1], b[nf2][2], b[nf2][3], bs_b + nf2*1280 + ks*32);
#pragma unroll
            for (int mf = 0; mf < 4; mf++)
#pragma unroll
                for (int nf = 0; nf < 8; nf++)
                    MMA16816(acc[mf][nf], a[mf], b[nf>>1][(nf&1)*2], b[nf>>1][(nf&1)*2+1]);
        }
        __syncthreads();
    }

    // stage accumulators to smem fp32 [128][132] for coalesced epilogue
    float* tile = (float*)smem;
    {
        int r = lane >> 2, cp = (lane & 3) * 2;
#pragma unroll
        for (int mf = 0; mf < 4; mf++)
#pragma unroll
            for (int nf = 0; nf < 8; nf++) {
                int rr = wm*64 + mf*16 + r, cc = wn*64 + nf*8 + cp;
                tile[rr*132 + cc]       = acc[mf][nf][0];
                tile[rr*132 + cc + 1]   = acc[mf][nf][1];
                tile[(rr+8)*132 + cc]   = acc[mf][nf][2];
                tile[(rr+8)*132 + cc+1] = acc[mf][nf][3];
            }
    }
    __syncthreads();

    if constexpr (EPI == 0) {
        if (n0 < 512) {              // Q (A-side [hi|lo|hi])
            for (int idx = tid; idx < 16384; idx += 128) {
                int r = idx >> 7, cc = idx & 127;
                float v = tile[r*132 + cc] + bias[n0 + cc];
                bf16 hi, lo; split2(v, hi, lo);
                bf16* row = g_q2 + (size_t)(m0 + r) * 1536;
                int n = n0 + cc;
                row[n] = hi; row[512 + n] = lo; row[1024 + n] = hi;
            }
        } else if (n0 < 1024) {      // K (B-side [hi|hi|lo])
            for (int idx = tid; idx < 16384; idx += 128) {
                int r = idx >> 7, cc = idx & 127;
                float v = tile[r*132 + cc] + bias[n0 + cc];
                bf16 hi, lo; split2(v, hi, lo);
                bf16* row = g_k2 + (size_t)(m0 + r) * 1536;
                int n = n0 + cc - 512;
                row[n] = hi; row[512 + n] = hi; row[1024 + n] = lo;
            }
        } else {                     // V -> transposed [B,C,3S] (B-side)
            for (int idx = tid; idx < 16384; idx += 128) {
                int rt = idx & 127, ct = idx >> 7;   // lanes along m(=s) for coalescing
                float v = tile[rt*132 + ct] + bias[n0 + ct];
                bf16 hi, lo; split2(v, hi, lo);
                int m = m0 + rt, b = m >> 10, s = m & 1023;
                int cg = n0 + ct - 1024;
                bf16* row = g_v2 + ((size_t)b*512 + cg) * 3072;
                row[s] = hi; row[1024 + s] = hi; row[2048 + s] = lo;
            }
        }
    } else if constexpr (EPI == 1) { // scores fp32
        float* op = Out + (size_t)z * SS * SS;
        for (int idx = tid; idx < 16384; idx += 128) {
            int r = idx >> 7, cc = idx & 127;
            op[(size_t)(m0 + r) * SS + n0 + cc] = tile[r*132 + cc] * scale;
        }
    } else if constexpr (EPI == 2) { // AV out (A-side)
        for (int idx = tid; idx < 16384; idx += 128) {
            int r = idx >> 7, cc = idx & 127;
            float v = tile[r*132 + cc];
            bf16 hi, lo; split2(v, hi, lo);
            bf16* row = g_ao2 + ((size_t)z * SS + m0 + r) * 1536;
            int n = n0 + cc;
            row[n] = hi; row[512 + n] = lo; row[1024 + n] = hi;
        }
    } else {                         // proj: +bias +residual, NCHW transposed write
        for (int idx = tid; idx < 16384; idx += 128) {
            int rt = idx & 127, ct = idx >> 7;
            int m = m0 + rt, b = m >> 10, s = m & 1023;
            int n = n0 + ct;
            size_t oidx = ((size_t)b * 512 + n) * 1024 + s;
            Out[oidx] = tile[rt*132 + ct] + bias[n] + resid[oidx];
        }
    }
}

// ---------------- softmax over 1024-wide rows, split output ----------------
__global__ void softmax_rows(const float* __restrict__ sc) {
    const float* row = sc + (size_t)blockIdx.x * SS;
    bf16* orow = g_p2 + (size_t)blockIdx.x * 3072;
    int t = threadIdx.x;
    float v[4];
#pragma unroll
    for (int i = 0; i < 4; i++) v[i] = row[t + i*256];
    float m = fmaxf(fmaxf(v[0], v[1]), fmaxf(v[2], v[3]));
    __shared__ float red[8];
    for (int o = 16; o > 0; o >>= 1) m = fmaxf(m, __shfl_xor_sync(0xffffffffu, m, o));
    if ((t & 31) == 0) red[t >> 5] = m;
    __syncthreads();
    float mm = fmaxf(fmaxf(fmaxf(red[0], red[1]), fmaxf(red[2], red[3])),
                     fmaxf(fmaxf(red[4], red[5]), fmaxf(red[6], red[7])));
    float s = 0.f;
#pragma unroll
    for (int i = 0; i < 4; i++) { v[i] = __expf(v[i] - mm); s += v[i]; }
    for (int o = 16; o > 0; o >>= 1) s += __shfl_xor_sync(0xffffffffu, s, o);
    __syncthreads();
    if ((t & 31) == 0) red[t >> 5] = s;
    __syncthreads();
    float tot = ((red[0]+red[1]) + (red[2]+red[3])) + ((red[4]+red[5]) + (red[6]+red[7]));
    float invs = 1.f / tot;
#pragma unroll
    for (int i = 0; i < 4; i++) {
        float p = v[i] * invs;
        bf16 hi, lo; split2(p, hi, lo);
        int k = t + i*256;
        orow[k] = hi; orow[1024 + k] = lo; orow[2048 + k] = hi;  // A-side [hi|lo|hi]
    }
}

// ---------------- launch ----------------
extern "C" void kernel_launch(void* const* d_in, const int* in_sizes, int n_in,
                              void* d_out, int out_size) {
    const float* x      = (const float*)d_in[0];
    const float* gn_w   = (const float*)d_in[1];
    const float* gn_b   = (const float*)d_in[2];
    const float* qkv_w  = (const float*)d_in[3];
    const float* qkv_b  = (const float*)d_in[4];
    const float* proj_w = (const float*)d_in[5];
    const float* proj_b = (const float*)d_in[6];
    float* out = (float*)d_out;

    cudaFuncSetAttribute(mm_gemm<0>, cudaFuncAttributeMaxDynamicSharedMemorySize, DYN_SMEM);
    cudaFuncSetAttribute(mm_gemm<1>, cudaFuncAttributeMaxDynamicSharedMemorySize, DYN_SMEM);
    cudaFuncSetAttribute(mm_gemm<2>, cudaFuncAttributeMaxDynamicSharedMemorySize, DYN_SMEM);
    cudaFuncSetAttribute(mm_gemm<3>, cudaFuncAttributeMaxDynamicSharedMemorySize, DYN_SMEM);

    bf16 *h2, *w1, *w2, *q2, *k2, *v2, *p2, *ao2; float* sc;
    cudaGetSymbolAddress((void**)&h2,  g_h2);
    cudaGetSymbolAddress((void**)&w1,  g_w1);
    cudaGetSymbolAddress((void**)&w2,  g_w2);
    cudaGetSymbolAddress((void**)&q2,  g_q2);
    cudaGetSymbolAddress((void**)&k2,  g_k2);
    cudaGetSymbolAddress((void**)&v2,  g_v2);
    cudaGetSymbolAddress((void**)&p2,  g_p2);
    cudaGetSymbolAddress((void**)&ao2, g_ao2);
    cudaGetSymbolAddress((void**)&sc,  g_sc);

    // 1. GroupNorm stats + normalize/transpose/split
    gn_partial<<<dim3(64, BB), 256>>>(x);
    gn_finalize<<<1, 32>>>();
    norm_split<<<dim3(SS/32, CC/32, BB), dim3(32, 8)>>>(x, gn_w, gn_b);

    // 2. weight splits
    wsplit<<<(1536*512 + 255)/256, 256>>>(qkv_w, w1, 1536*512);
    wsplit<<<( 512*512 + 255)/256, 256>>>(proj_w, w2, 512*512);

    // 3. QKV GEMM: M=16384, N=1536, K=1536
    mm_gemm<0><<<dim3(12, 128, 1), 128, DYN_SMEM>>>(
        h2, 1536, 0LL, w1, 1536, 0LL, nullptr, qkv_b, nullptr, 1.f, 1536);

    // 4. scores = scale * Q K^T, batched: M=N=1024, K=1536
    mm_gemm<1><<<dim3(8, 8, BB), 128, DYN_SMEM>>>(
        q2, 1536, 1024LL*1536, k2, 1536, 1024LL*1536, sc,
        nullptr, nullptr, 0.044194173824159216f, 1536);

    // 5. softmax + split
    softmax_rows<<<BB*SS, 256>>>(sc);

    // 6. attn @ V: M=1024, N=512, K=3072, batched
    mm_gemm<2><<<dim3(4, 8, BB), 128, DYN_SMEM>>>(
        p2, 3072, 1024LL*3072, v2, 3072, 512LL*3072, nullptr,
        nullptr, nullptr, 1.f, 3072);

    // 7. proj + bias + residual -> NCHW out: M=16384, N=512, K=1536
    mm_gemm<3><<<dim3(4, 128, 1), 128, DYN_SMEM>>>(
        ao2, 1536, 0LL, w2, 1536, 0LL, out, proj_b, x, 1.f, 1536);
}

// round 4
// speedup vs baseline: 1.9632x; 1.3318x over previous
#include <cuda_runtime.h>
#include <cuda_bf16.h>
#include <cstdint>
#include <math.h>

#define BB 16
#define CC 512
#define SS 1024
#define PER_B (CC*SS)

typedef __nv_bfloat16 bf16;

// ---------------- scratch (__device__ globals; no allocs) ----------------
__device__ float g_psum[BB*64], g_psq[BB*64], g_stats[BB*2];
__device__ bf16  g_h2 [(size_t)BB*SS*1024];   // norm'd [B*S, hi|lo]  (A-side, fold 1024)
__device__ bf16  g_w1 [1536*1024];            // qkv_w  [hi|lo]      (B-side, fold 512)
__device__ bf16  g_w2 [512*1024];             // proj_w [hi|lo]      (B-side, fold 512)
__device__ bf16  g_q2 [(size_t)BB*SS*1024];   // Q [hi|lo] (A-side)
__device__ bf16  g_k2 [(size_t)BB*SS*1024];   // K [hi|lo] (B-side)
__device__ bf16  g_v2 [(size_t)BB*CC*2048];   // V transposed [B,C, hi|lo over S] (B-side, fold 1024)
__device__ bf16  g_p2 [(size_t)BB*SS*2048];   // probs [B*S, hi|lo] (A-side, fold 2048)
__device__ bf16  g_ao2[(size_t)BB*SS*1024];   // attn out [hi|lo] (A-side)
__device__ float g_sc [(size_t)BB*SS*SS];     // scores fp32

// ---------------- helpers ----------------
__device__ __forceinline__ uint32_t smem_u32(const void* p) {
    uint32_t a;
    asm("{ .reg .u64 t; cvta.to.shared.u64 t, %1; cvt.u32.u64 %0, t; }" : "=r"(a) : "l"(p));
    return a;
}
#define CP_ASYNC16(dst, src) \
    asm volatile("cp.async.cg.shared.global [%0], [%1], 16;" :: "r"(dst), "l"(src) : "memory")
#define CP_COMMIT() asm volatile("cp.async.commit_group;" ::: "memory")
#define CP_WAIT0()  asm volatile("cp.async.wait_group 0;" ::: "memory")
#define CP_WAIT1()  asm volatile("cp.async.wait_group 1;" ::: "memory")
#define LDM_X4(r0,r1,r2,r3,addr) \
    asm volatile("ldmatrix.sync.aligned.m8n8.x4.shared.b16 {%0,%1,%2,%3}, [%4];" \
        : "=r"(r0),"=r"(r1),"=r"(r2),"=r"(r3) : "r"(addr))
#define MMA16816(d, a, b0, b1) \
    asm volatile("mma.sync.aligned.m16n8k16.row.col.f32.bf16.bf16.f32 " \
        "{%0,%1,%2,%3}, {%4,%5,%6,%7}, {%8,%9}, {%0,%1,%2,%3};" \
        : "+f"((d)[0]), "+f"((d)[1]), "+f"((d)[2]), "+f"((d)[3]) \
        : "r"((a)[0]), "r"((a)[1]), "r"((a)[2]), "r"((a)[3]), "r"(b0), "r"(b1))

__device__ __forceinline__ void split2(float v, bf16& hi, bf16& lo) {
    hi = __float2bfloat16(v);
    lo = __float2bfloat16(v - __bfloat162float(hi));
}

// ---------------- GroupNorm stats ----------------
__global__ void gn_partial(const float* __restrict__ x) {
    int b = blockIdx.y, chunk = blockIdx.x, t = threadIdx.x;
    const float* p = x + (size_t)b*PER_B + (size_t)chunk*8192;
    float s = 0.f, q = 0.f;
#pragma unroll
    for (int i = 0; i < 32; i++) { float v = p[t + i*256]; s += v; q += v*v; }
    __shared__ float ss_[8], sq_[8];
    for (int o = 16; o > 0; o >>= 1) {
        s += __shfl_down_sync(0xffffffffu, s, o);
        q += __shfl_down_sync(0xffffffffu, q, o);
    }
    if ((t & 31) == 0) { ss_[t >> 5] = s; sq_[t >> 5] = q; }
    __syncthreads();
    if (t == 0) {
        float S2 = 0.f, Q2 = 0.f;
#pragma unroll
        for (int i = 0; i < 8; i++) { S2 += ss_[i]; Q2 += sq_[i]; }
        g_psum[b*64 + chunk] = S2; g_psq[b*64 + chunk] = Q2;
    }
}
__global__ void gn_finalize() {
    int b = threadIdx.x;
    if (b < BB) {
        float s = 0.f, q = 0.f;
        for (int i = 0; i < 64; i++) { s += g_psum[b*64+i]; q += g_psq[b*64+i]; }
        float mean = s * (1.f/(float)PER_B);
        float var  = q * (1.f/(float)PER_B) - mean*mean;
        g_stats[2*b] = mean; g_stats[2*b+1] = rsqrtf(var + 1e-5f);
    }
}

// ---------------- normalize + transpose + split -> g_h2 [B*S, hi|lo] ----------------
__global__ void norm_split(const float* __restrict__ x,
                           const float* __restrict__ gw,
                           const float* __restrict__ gb) {
    __shared__ float tile[32][33];
    int b = blockIdx.z;
    int s0 = blockIdx.x * 32, c0 = blockIdx.y * 32;
    int tx = threadIdx.x, ty = threadIdx.y;
    const float* xp = x + (size_t)b * PER_B;
#pragma unroll
    for (int i = 0; i < 4; i++) {
        int c = c0 + ty + i*8;
        tile[ty + i*8][tx] = xp[(size_t)c*SS + s0 + tx];
    }
    __syncthreads();
    float mean = g_stats[2*b], inv = g_stats[2*b+1];
    int c = c0 + tx;
    float w  = gw[c] * inv;
    float bias = gb[c] - mean * w;
#pragma unroll
    for (int i = 0; i < 4; i++) {
        int s = s0 + ty + i*8;
        float v = tile[tx][ty + i*8] * w + bias;
        bf16 hi, lo; split2(v, hi, lo);
        bf16* row = g_h2 + ((size_t)b*SS + s) * 1024;
        row[c] = hi; row[512 + c] = lo;
    }
}

// ---------------- weight split (stored [hi|lo]) ----------------
__global__ void wsplit(const float* __restrict__ src, bf16* __restrict__ dst, int total) {
    int i = blockIdx.x * 256 + threadIdx.x;
    if (i < total) {
        int r = i >> 9, c = i & 511;
        bf16 hi, lo; split2(src[i], hi, lo);
        bf16* row = dst + (size_t)r * 1024;
        row[c] = hi; row[512 + c] = lo;
    }
}

// ---------------- HMMA GEMM: 128x128 CTA, 8 warps (32x64 each), BK=32, 3-stage ----------------
// NT logical: out[m,n] = sum_k A[m,k_effA]*B[n,k_effB], k_eff = k>=thresh ? k-thresh : k
// EPI: 0 = QKV split-out, 1 = scores*scale, 2 = AV split-out, 3 = proj+bias+resid (NCHW)
#define DYN_SMEM 69632
#define STAGE_BYTES 20480        // A(10240) + B(10240); 80B row stride

__device__ __forceinline__ void prefetch_tile(char* smem, int stage,
    const bf16* __restrict__ A, int lda, const bf16* __restrict__ B, int ldb,
    int m0, int n0, int kA, int kB, int tid)
{
    char* as = smem + stage*STAGE_BYTES;
    char* bs = as + 10240;
    int row = tid >> 1, seg = tid & 1;
    const bf16* ag = A + (size_t)(m0 + row)*lda + kA + seg*16;
    const bf16* bg = B + (size_t)(n0 + row)*ldb + kB + seg*16;
    uint32_t asw = smem_u32(as + row*80 + seg*32);
    uint32_t bsw = smem_u32(bs + row*80 + seg*32);
    CP_ASYNC16(asw,      (const void*)ag);
    CP_ASYNC16(asw + 16, (const void*)(ag + 8));
    CP_ASYNC16(bsw,      (const void*)bg);
    CP_ASYNC16(bsw + 16, (const void*)(bg + 8));
}

template<int EPI>
__global__ __launch_bounds__(256, 2)
void mm_gemm(const bf16* __restrict__ A, int lda, long long sA, int thA,
             const bf16* __restrict__ B, int ldb, long long sB, int thB,
             float* __restrict__ Out,
             const float* __restrict__ bias,
             const float* __restrict__ resid,
             float scale, int K)
{
    extern __shared__ char smem[];
    int tid = threadIdx.x, lane = tid & 31, wid = tid >> 5;
    int wm = wid >> 1, wn = wid & 1;          // 4 x 2 warp grid, 32x64 tiles
    int z = blockIdx.z;
    int m0 = blockIdx.y * 128, n0 = blockIdx.x * 128;
    A += (size_t)z * sA;
    B += (size_t)z * sB;

    float acc[2][8][4];
#pragma unroll
    for (int i = 0; i < 2; i++)
#pragma unroll
        for (int j = 0; j < 8; j++)
#pragma unroll
            for (int r = 0; r < 4; r++) acc[i][j][r] = 0.f;

    uint32_t a_off = (uint32_t)((wm*32 + (lane & 15)) * 80 + (lane >> 4) * 16);
    uint32_t b_off = (uint32_t)((wn*64 + (lane & 7) + ((lane >> 4) << 3)) * 80
                                + ((lane >> 3) & 1) * 16);
    uint32_t smem_base = smem_u32(smem);

    int nch = K >> 5;
    {
        int k0 = 0;
        prefetch_tile(smem, 0, A, lda, B, ldb, m0, n0,
                      (k0 >= thA) ? k0 - thA : k0, (k0 >= thB) ? k0 - thB : k0, tid);
        CP_COMMIT();
        k0 = 32;
        prefetch_tile(smem, 1, A, lda, B, ldb, m0, n0,
                      (k0 >= thA) ? k0 - thA : k0, (k0 >= thB) ? k0 - thB : k0, tid);
        CP_COMMIT();
    }

    int st = 0;
    for (int c = 0; c < nch; c++) {
        if (c + 2 <= nch) CP_WAIT1(); else CP_WAIT0();
        __syncthreads();
        if (c + 2 < nch) {
            int k0 = (c + 2) * 32;
            int nst = st + 2; if (nst >= 3) nst -= 3;
            prefetch_tile(smem, nst, A, lda, B, ldb, m0, n0,
                          (k0 >= thA) ? k0 - thA : k0, (k0 >= thB) ? k0 - thB : k0, tid);
            CP_COMMIT();
        }

        uint32_t as_b = smem_base + st*STAGE_BYTES + a_off;
        uint32_t bs_b = smem_base + st*STAGE_BYTES + 10240 + b_off;
#pragma unroll
        for (int ks = 0; ks < 2; ks++) {
            uint32_t a[2][4], b[4][4];
#pragma unroll
            for (int mf = 0; mf < 2; mf++)
                LDM_X4(a[mf][0], a[mf][1], a[mf][2], a[mf][3], as_b + mf*1280 + ks*32);
#pragma unroll
            for (int nf2 = 0; nf2 < 4; nf2++)
                LDM_X4(b[nf2][0], b[nf2][1], b[nf2][2], b[nf2][3], bs_b + nf2*1280 + ks*32);
#pragma unroll
            for (int mf = 0; mf < 2; mf++)
#pragma unroll
                for (int nf = 0; nf < 8; nf++)
                    MMA16816(acc[mf][nf], a[mf], b[nf>>1][(nf&1)*2], b[nf>>1][(nf&1)*2+1]);
        }
        if (++st == 3) st = 0;
    }
    __syncthreads();

    // stage accumulators to smem fp32 [128][132]
    float* tile = (float*)smem;
    {
        int r = lane >> 2, cp = (lane & 3) * 2;
#pragma unroll
        for (int mf = 0; mf < 2; mf++)
#pragma unroll
            for (int nf = 0; nf < 8; nf++) {
                int rr = wm*32 + mf*16 + r, cc = wn*64 + nf*8 + cp;
                tile[rr*132 + cc]       = acc[mf][nf][0];
                tile[rr*132 + cc + 1]   = acc[mf][nf][1];
                tile[(rr+8)*132 + cc]   = acc[mf][nf][2];
                tile[(rr+8)*132 + cc+1] = acc[mf][nf][3];
            }
    }
    __syncthreads();

    if constexpr (EPI == 0) {
        if (n0 < 512) {              // Q (A-side [hi|lo])
            for (int idx = tid; idx < 16384; idx += 256) {
                int r = idx >> 7, cc = idx & 127;
                float v = tile[r*132 + cc] + bias[n0 + cc];
                bf16 hi, lo; split2(v, hi, lo);
                bf16* row = g_q2 + (size_t)(m0 + r) * 1024;
                int n = n0 + cc;
                row[n] = hi; row[512 + n] = lo;
            }
        } else if (n0 < 1024) {      // K (B-side [hi|lo])
            for (int idx = tid; idx < 16384; idx += 256) {
                int r = idx >> 7, cc = idx & 127;
                float v = tile[r*132 + cc] + bias[n0 + cc];
                bf16 hi, lo; split2(v, hi, lo);
                bf16* row = g_k2 + (size_t)(m0 + r) * 1024;
                int n = n0 + cc - 512;
                row[n] = hi; row[512 + n] = lo;
            }
        } else {                     // V -> transposed [B,C, hi|lo over S]
            for (int idx = tid; idx < 16384; idx += 256) {
                int rt = idx & 127, ct = idx >> 7;
                float v = tile[rt*132 + ct] + bias[n0 + ct];
                bf16 hi, lo; split2(v, hi, lo);
                int m = m0 + rt, b = m >> 10, s = m & 1023;
                int cg = n0 + ct - 1024;
                bf16* row = g_v2 + ((size_t)b*512 + cg) * 2048;
                row[s] = hi; row[1024 + s] = lo;
            }
        }
    } else if constexpr (EPI == 1) { // scores fp32
        float* op = Out + (size_t)z * SS * SS;
        for (int idx = tid; idx < 16384; idx += 256) {
            int r = idx >> 7, cc = idx & 127;
            op[(size_t)(m0 + r) * SS + n0 + cc] = tile[r*132 + cc] * scale;
        }
    } else if constexpr (EPI == 2) { // AV out (A-side [hi|lo])
        for (int idx = tid; idx < 16384; idx += 256) {
            int r = idx >> 7, cc = idx & 127;
            float v = tile[r*132 + cc];
            bf16 hi, lo; split2(v, hi, lo);
            bf16* row = g_ao2 + ((size_t)z * SS + m0 + r) * 1024;
            int n = n0 + cc;
            row[n] = hi; row[512 + n] = lo;
        }
    } else {                         // proj: +bias +residual, NCHW transposed write
        for (int idx = tid; idx < 16384; idx += 256) {
            int rt = idx & 127, ct = idx >> 7;
            int m = m0 + rt, b = m >> 10, s = m & 1023;
            int n = n0 + ct;
            size_t oidx = ((size_t)b * 512 + n) * 1024 + s;
            Out[oidx] = tile[rt*132 + ct] + bias[n] + resid[oidx];
        }
    }
}

// ---------------- softmax over 1024-wide rows, [hi|lo] output ----------------
__global__ void softmax_rows(const float* __restrict__ sc) {
    const float* row = sc + (size_t)blockIdx.x * SS;
    bf16* orow = g_p2 + (size_t)blockIdx.x * 2048;
    int t = threadIdx.x;
    float v[4];
#pragma unroll
    for (int i = 0; i < 4; i++) v[i] = row[t + i*256];
    float m = fmaxf(fmaxf(v[0], v[1]), fmaxf(v[2], v[3]));
    __shared__ float red[8];
    for (int o = 16; o > 0; o >>= 1) m = fmaxf(m, __shfl_xor_sync(0xffffffffu, m, o));
    if ((t & 31) == 0) red[t >> 5] = m;
    __syncthreads();
    float mm = fmaxf(fmaxf(fmaxf(red[0], red[1]), fmaxf(red[2], red[3])),
                     fmaxf(fmaxf(red[4], red[5]), fmaxf(red[6], red[7])));
    float s = 0.f;
#pragma unroll
    for (int i = 0; i < 4; i++) { v[i] = __expf(v[i] - mm); s += v[i]; }
    for (int o = 16; o > 0; o >>= 1) s += __shfl_xor_sync(0xffffffffu, s, o);
    __syncthreads();
    if ((t & 31) == 0) red[t >> 5] = s;
    __syncthreads();
    float tot = ((red[0]+red[1]) + (red[2]+red[3])) + ((red[4]+red[5]) + (red[6]+red[7]));
    float invs = 1.f / tot;
#pragma unroll
    for (int i = 0; i < 4; i++) {
        float p = v[i] * invs;
        bf16 hi, lo; split2(p, hi, lo);
        int k = t + i*256;
        orow[k] = hi; orow[1024 + k] = lo;
    }
}

// ---------------- launch ----------------
extern "C" void kernel_launch(void* const* d_in, const int* in_sizes, int n_in,
                              void* d_out, int out_size) {
    const float* x      = (const float*)d_in[0];
    const float* gn_w   = (const float*)d_in[1];
    const float* gn_b   = (const float*)d_in[2];
    const float* qkv_w  = (const float*)d_in[3];
    const float* qkv_b  = (const float*)d_in[4];
    const float* proj_w = (const float*)d_in[5];
    const float* proj_b = (const float*)d_in[6];
    float* out = (float*)d_out;

    cudaFuncSetAttribute(mm_gemm<0>, cudaFuncAttributeMaxDynamicSharedMemorySize, DYN_SMEM);
    cudaFuncSetAttribute(mm_gemm<1>, cudaFuncAttributeMaxDynamicSharedMemorySize, DYN_SMEM);
    cudaFuncSetAttribute(mm_gemm<2>, cudaFuncAttributeMaxDynamicSharedMemorySize, DYN_SMEM);
    cudaFuncSetAttribute(mm_gemm<3>, cudaFuncAttributeMaxDynamicSharedMemorySize, DYN_SMEM);

    bf16 *h2, *w1, *w2, *q2, *k2, *v2, *p2, *ao2; float* sc;
    cudaGetSymbolAddress((void**)&h2,  g_h2);
    cudaGetSymbolAddress((void**)&w1,  g_w1);
    cudaGetSymbolAddress((void**)&w2,  g_w2);
    cudaGetSymbolAddress((void**)&q2,  g_q2);
    cudaGetSymbolAddress((void**)&k2,  g_k2);
    cudaGetSymbolAddress((void**)&v2,  g_v2);
    cudaGetSymbolAddress((void**)&p2,  g_p2);
    cudaGetSymbolAddress((void**)&ao2, g_ao2);
    cudaGetSymbolAddress((void**)&sc,  g_sc);

    // 1-2. weight splits first (so ncu -s 5 lands on mm_gemm<0>)
    wsplit<<<(1536*512 + 255)/256, 256>>>(qkv_w, w1, 1536*512);
    wsplit<<<( 512*512 + 255)/256, 256>>>(proj_w, w2, 512*512);

    // 3-5. GroupNorm stats + normalize/transpose/split
    gn_partial<<<dim3(64, BB), 256>>>(x);
    gn_finalize<<<1, 32>>>();
    norm_split<<<dim3(SS/32, CC/32, BB), dim3(32, 8)>>>(x, gn_w, gn_b);

    // 6. QKV GEMM: M=16384, N=1536, K=1536 (logical)
    mm_gemm<0><<<dim3(12, 128, 1), 256, DYN_SMEM>>>(
        h2, 1024, 0LL, 1024, w1, 1024, 0LL, 512,
        nullptr, qkv_b, nullptr, 1.f, 1536);

    // 7. scores = scale * Q K^T, batched: M=N=1024, K=1536 (logical)
    mm_gemm<1><<<dim3(8, 8, BB), 256, DYN_SMEM>>>(
        q2, 1024, 1024LL*1024, 1024, k2, 1024, 1024LL*1024, 512, sc,
        nullptr, nullptr, 0.044194173824159216f, 1536);

    // 8. softmax + split
    softmax_rows<<<BB*SS, 256>>>(sc);

    // 9. attn @ V: M=1024, N=512, K=3072 (logical), batched
    mm_gemm<2><<<dim3(4, 8, BB), 256, DYN_SMEM>>>(
        p2, 2048, 1024LL*2048, 2048, v2, 2048, 512LL*2048, 1024, nullptr,
        nullptr, nullptr, 1.f, 3072);

    // 10. proj + bias + residual -> NCHW out: M=16384, N=512, K=1536 (logical)
    mm_gemm<3><<<dim3(4, 128, 1), 256, DYN_SMEM>>>(
        ao2, 1024, 0LL, 1024, w2, 1024, 0LL, 512, out, proj_b, x, 1.f, 1536);
}